// round 1
// baseline (speedup 1.0000x reference)
#include <cuda_runtime.h>
#include <float.h>
#include <math.h>

#define T_   2048
#define D_   1024
#define H_   704
#define E_   16
#define HS_  1408
#define KSEL 4
#define ROUTE_SCALE_ 2.5446f

// ---------------- static device scratch (no runtime allocation) ----------------
__device__ float g_hg[(size_t)E_ * T_ * H_];   // routed gate-proj (then swiglu result)
__device__ float g_hu[(size_t)E_ * T_ * H_];   // routed up-proj
__device__ float g_po[(size_t)E_ * T_ * D_];   // routed down-proj per pair
__device__ float g_sg[(size_t)T_ * HS_];       // shared gate-proj (then swiglu result)
__device__ float g_su[(size_t)T_ * HS_];       // shared up-proj
__device__ int   g_cnt[E_];
__device__ int   g_etok[E_ * T_];
__device__ int   g_slot[T_ * KSEL];
__device__ float g_wt[T_ * KSEL];

// ---------------- packed f32x2 helpers ----------------
__device__ __forceinline__ unsigned long long pk2(float lo, float hi) {
    unsigned long long r;
    asm("mov.b64 %0, {%1,%2};" : "=l"(r) : "f"(lo), "f"(hi));
    return r;
}
__device__ __forceinline__ void fma2(unsigned long long& d,
                                     unsigned long long a, unsigned long long b) {
    asm("fma.rn.f32x2 %0, %1, %2, %0;" : "+l"(d) : "l"(a), "l"(b));
}
__device__ __forceinline__ void upk2(unsigned long long v, float& lo, float& hi) {
    asm("mov.b64 {%0,%1}, %2;" : "=f"(lo), "=f"(hi) : "l"(v));
}

// ---------------- zero counts ----------------
__global__ void zero_cnt_kernel() {
    if (threadIdx.x < E_) g_cnt[threadIdx.x] = 0;
}

// ---------------- gate: logits + DeepSeek-V3 routing + dispatch ----------------
__global__ void gate_kernel(const float* __restrict__ x,
                            const float* __restrict__ gw,
                            const float* __restrict__ gb) {
    __shared__ __align__(16) float xs[8][D_];
    const int warp = threadIdx.x >> 5;
    const int lane = threadIdx.x & 31;
    const int t = blockIdx.x * 8 + warp;

    const float* xr = x + (size_t)t * D_;
    // cooperative row load into smem (coalesced float4)
    for (int i = lane; i < D_ / 4; i += 32)
        ((float4*)xs[warp])[i] = ((const float4*)xr)[i];
    __syncwarp();

    float lgv[E_];
#pragma unroll
    for (int e = 0; e < E_; e++) {
        const float* wr = gw + (size_t)e * D_;
        float p = 0.f;
        for (int i = lane; i < D_; i += 32) p += xs[warp][i] * wr[i];
#pragma unroll
        for (int o = 16; o; o >>= 1) p += __shfl_xor_sync(0xffffffffu, p, o);
        lgv[e] = p;   // all lanes hold full sum after bfly reduce
    }

    if (lane == 0) {
        float sc[E_], r[E_];
#pragma unroll
        for (int e = 0; e < E_; e++) {
            sc[e] = 1.f / (1.f + expf(-lgv[e]));
            r[e]  = sc[e] + gb[e];
        }
        // group scores = sum of top-2 routing scores in each group of 4
        float gs[4];
#pragma unroll
        for (int g = 0; g < 4; g++) {
            float m1 = -FLT_MAX, m2 = -FLT_MAX;
#pragma unroll
            for (int j = 0; j < 4; j++) {
                float v = r[4 * g + j];
                if (v > m1) { m2 = m1; m1 = v; }
                else if (v > m2) { m2 = v; }
            }
            gs[g] = m1 + m2;
        }
        // top-2 groups (lowest index wins ties, matching lax.top_k)
        int g1 = 0;
#pragma unroll
        for (int g = 1; g < 4; g++) if (gs[g] > gs[g1]) g1 = g;
        int g2 = -1;
#pragma unroll
        for (int g = 0; g < 4; g++) {
            if (g == g1) continue;
            if (g2 < 0 || gs[g] > gs[g2]) g2 = g;
        }
        // mask non-kept groups
#pragma unroll
        for (int e = 0; e < E_; e++) {
            int g = e >> 2;
            if (g != g1 && g != g2) r[e] = -FLT_MAX;
        }
        // top-4 experts by masked routing score
        int idx[KSEL];
        float wsum = 0.f;
#pragma unroll
        for (int k = 0; k < KSEL; k++) {
            int b = 0; float bv = -FLT_MAX;
#pragma unroll
            for (int e = 0; e < E_; e++) {
                if (r[e] > bv) { bv = r[e]; b = e; }
            }
            idx[k] = b;
            r[b] = -FLT_MAX;
            wsum += sc[b];
        }
        wsum = fmaxf(wsum, 1e-9f);
#pragma unroll
        for (int k = 0; k < KSEL; k++) {
            int e = idx[k];
            float wk = sc[e] / wsum * ROUTE_SCALE_;
            int pos = atomicAdd(&g_cnt[e], 1);
            g_etok[e * T_ + pos] = t;
            g_slot[t * KSEL + k] = e * T_ + pos;
            g_wt[t * KSEL + k]   = wk;
        }
    }
}

// ---------------- generic SGEMM-TN: C[M,N] = A[M,Kd] * B[N,Kd]^T ----------------
// blockIdx.z selects expert; optional per-expert count (early exit) and row gather.
// Tiles: BM=128, BN=64, BK=16, 256 threads, 8x4 per-thread via f32x2 (4 m-pairs x 4 n).
#define BM 128
#define BN 64
#define BKK 16

__global__ __launch_bounds__(256) void sgemm_tn(
    const float* __restrict__ A, long long aStride, int Kd,
    const float* __restrict__ B, long long bStride,
    float* __restrict__ C, long long cStride, int N,
    int M, const int* __restrict__ cnt,
    const int* __restrict__ gather) {
    const int z  = blockIdx.z;
    const int Me = cnt ? cnt[z] : M;
    const int m0 = blockIdx.y * BM;
    if (m0 >= Me) return;

    __shared__ __align__(16) float As[2][BKK][132];   // padded: conflict-free STS
    __shared__ __align__(16) float Bs[2][BKK][68];

    const int tid  = threadIdx.x;
    const int lrow = tid >> 2;           // 0..63
    const int lk4  = (tid & 3) * 4;      // 0,4,8,12

    const float* Az = A + (size_t)z * aStride;
    const float* Bz = B + (size_t)z * bStride + (size_t)blockIdx.x * BN * Kd;
    float*       Cz = C + (size_t)z * cStride;

    const float* ap0;
    const float* ap1;
    {
        int r0 = m0 + lrow, r1 = m0 + lrow + 64;
        if (gather) {
            int t0 = (r0 < Me) ? gather[z * T_ + r0] : 0;
            int t1 = (r1 < Me) ? gather[z * T_ + r1] : 0;
            ap0 = Az + (size_t)t0 * Kd;
            ap1 = Az + (size_t)t1 * Kd;
        } else {
            ap0 = Az + (size_t)r0 * Kd;
            ap1 = Az + (size_t)r1 * Kd;
        }
    }
    const float* bp = Bz + (size_t)lrow * Kd;

    const int ty = tid >> 4;   // 0..15 -> 8 rows
    const int tx = tid & 15;   // 0..15 -> 4 cols

    unsigned long long acc[4][4];
#pragma unroll
    for (int i = 0; i < 4; i++)
#pragma unroll
        for (int j = 0; j < 4; j++) acc[i][j] = 0ull;

    const int KT = Kd / BKK;

    // prologue: stage tile 0
    {
        float4 la0 = *(const float4*)(ap0 + lk4);
        float4 la1 = *(const float4*)(ap1 + lk4);
        float4 lb  = *(const float4*)(bp + lk4);
#pragma unroll
        for (int j = 0; j < 4; j++) {
            As[0][lk4 + j][lrow]      = (&la0.x)[j];
            As[0][lk4 + j][lrow + 64] = (&la1.x)[j];
            Bs[0][lk4 + j][lrow]      = (&lb.x)[j];
        }
    }
    __syncthreads();

    for (int kt = 0; kt < KT; kt++) {
        const int cur = kt & 1;
        float4 na0, na1, nb;
        if (kt + 1 < KT) {
            const int ko = (kt + 1) * BKK + lk4;
            na0 = *(const float4*)(ap0 + ko);
            na1 = *(const float4*)(ap1 + ko);
            nb  = *(const float4*)(bp + ko);
        }
#pragma unroll
        for (int kk = 0; kk < BKK; kk++) {
            float4 av0 = *(const float4*)&As[cur][kk][ty * 8];
            float4 av1 = *(const float4*)&As[cur][kk][ty * 8 + 4];
            float4 bv  = *(const float4*)&Bs[cur][kk][tx * 4];
            unsigned long long am0 = pk2(av0.x, av0.y);
            unsigned long long am1 = pk2(av0.z, av0.w);
            unsigned long long am2 = pk2(av1.x, av1.y);
            unsigned long long am3 = pk2(av1.z, av1.w);
            unsigned long long bb0 = pk2(bv.x, bv.x);
            unsigned long long bb1 = pk2(bv.y, bv.y);
            unsigned long long bb2 = pk2(bv.z, bv.z);
            unsigned long long bb3 = pk2(bv.w, bv.w);
            fma2(acc[0][0], am0, bb0); fma2(acc[0][1], am0, bb1);
            fma2(acc[0][2], am0, bb2); fma2(acc[0][3], am0, bb3);
            fma2(acc[1][0], am1, bb0); fma2(acc[1][1], am1, bb1);
            fma2(acc[1][2], am1, bb2); fma2(acc[1][3], am1, bb3);
            fma2(acc[2][0], am2, bb0); fma2(acc[2][1], am2, bb1);
            fma2(acc[2][2], am2, bb2); fma2(acc[2][3], am2, bb3);
            fma2(acc[3][0], am3, bb0); fma2(acc[3][1], am3, bb1);
            fma2(acc[3][2], am3, bb2); fma2(acc[3][3], am3, bb3);
        }
        if (kt + 1 < KT) {
            const int nxt = cur ^ 1;
#pragma unroll
            for (int j = 0; j < 4; j++) {
                As[nxt][lk4 + j][lrow]      = (&na0.x)[j];
                As[nxt][lk4 + j][lrow + 64] = (&na1.x)[j];
                Bs[nxt][lk4 + j][lrow]      = (&nb.x)[j];
            }
            __syncthreads();
        }
    }

    const int crow = m0 + ty * 8;
    const int ccol = blockIdx.x * BN + tx * 4;
#pragma unroll
    for (int mp = 0; mp < 4; mp++) {
        float lo0, hi0, lo1, hi1, lo2, hi2, lo3, hi3;
        upk2(acc[mp][0], lo0, hi0);
        upk2(acc[mp][1], lo1, hi1);
        upk2(acc[mp][2], lo2, hi2);
        upk2(acc[mp][3], lo3, hi3);
        float4 r0 = make_float4(lo0, lo1, lo2, lo3);
        float4 r1 = make_float4(hi0, hi1, hi2, hi3);
        *(float4*)(Cz + (size_t)(crow + 2 * mp) * N + ccol)     = r0;
        *(float4*)(Cz + (size_t)(crow + 2 * mp + 1) * N + ccol) = r1;
    }
}

// ---------------- SwiGLU elementwise ----------------
__global__ void swiglu_routed_kernel() {
    size_t i = (size_t)blockIdx.x * blockDim.x + threadIdx.x;  // float4 index
    int row = (int)(i / (H_ / 4));
    int e = row >> 11;        // /2048
    int r = row & (T_ - 1);
    if (r >= g_cnt[e]) return;
    float4* hg4 = (float4*)g_hg;
    const float4* hu4 = (const float4*)g_hu;
    float4 g = hg4[i], u = hu4[i];
    g.x = g.x / (1.f + expf(-g.x)) * u.x;
    g.y = g.y / (1.f + expf(-g.y)) * u.y;
    g.z = g.z / (1.f + expf(-g.z)) * u.z;
    g.w = g.w / (1.f + expf(-g.w)) * u.w;
    hg4[i] = g;
}

__global__ void swiglu_shared_kernel() {
    size_t i = (size_t)blockIdx.x * blockDim.x + threadIdx.x;  // float4 index
    float4* sg4 = (float4*)g_sg;
    const float4* su4 = (const float4*)g_su;
    float4 g = sg4[i], u = su4[i];
    g.x = g.x / (1.f + expf(-g.x)) * u.x;
    g.y = g.y / (1.f + expf(-g.y)) * u.y;
    g.z = g.z / (1.f + expf(-g.z)) * u.z;
    g.w = g.w / (1.f + expf(-g.w)) * u.w;
    sg4[i] = g;
}

// ---------------- combine: out += sum_k w_k * pair_out[slot_k] ----------------
__global__ void combine_kernel(float* __restrict__ out) {
    int t = blockIdx.x;
    int c = threadIdx.x;   // 0..255 float4 columns (D_/4)
    float4 a = ((float4*)out)[(size_t)t * (D_ / 4) + c];
#pragma unroll
    for (int k = 0; k < KSEL; k++) {
        int s = g_slot[t * KSEL + k];
        float wk = g_wt[t * KSEL + k];
        float4 v = ((const float4*)g_po)[(size_t)s * (D_ / 4) + c];
        a.x += wk * v.x; a.y += wk * v.y; a.z += wk * v.z; a.w += wk * v.w;
    }
    ((float4*)out)[(size_t)t * (D_ / 4) + c] = a;
}

// ---------------- launch ----------------
extern "C" void kernel_launch(void* const* d_in, const int* in_sizes, int n_in,
                              void* d_out, int out_size) {
    (void)in_sizes; (void)n_in; (void)out_size;
    const float* x   = (const float*)d_in[0];
    const float* gw  = (const float*)d_in[1];
    const float* gb  = (const float*)d_in[2];
    const float* w1  = (const float*)d_in[3];
    const float* w3  = (const float*)d_in[4];
    const float* w2  = (const float*)d_in[5];
    const float* ws1 = (const float*)d_in[6];
    const float* ws3 = (const float*)d_in[7];
    const float* ws2 = (const float*)d_in[8];
    float* out = (float*)d_out;

    float *hg, *hu, *po, *sg, *su;
    int *cnt, *etok;
    cudaGetSymbolAddress((void**)&hg,   g_hg);
    cudaGetSymbolAddress((void**)&hu,   g_hu);
    cudaGetSymbolAddress((void**)&po,   g_po);
    cudaGetSymbolAddress((void**)&sg,   g_sg);
    cudaGetSymbolAddress((void**)&su,   g_su);
    cudaGetSymbolAddress((void**)&cnt,  g_cnt);
    cudaGetSymbolAddress((void**)&etok, g_etok);

    zero_cnt_kernel<<<1, 32>>>();
    gate_kernel<<<T_ / 8, 256>>>(x, gw, gb);

    // routed: gate & up projections ([pairs x H] = gathered x @ w1/w3^T)
    sgemm_tn<<<dim3(H_ / BN, T_ / BM, E_), 256>>>(
        x, 0LL, D_, w1, (long long)H_ * D_, hg, (long long)T_ * H_, H_, 0, cnt, etok);
    sgemm_tn<<<dim3(H_ / BN, T_ / BM, E_), 256>>>(
        x, 0LL, D_, w3, (long long)H_ * D_, hu, (long long)T_ * H_, H_, 0, cnt, etok);
    swiglu_routed_kernel<<<(E_ * T_ * (H_ / 4)) / 256, 256>>>();
    // routed: down projection ([pairs x D] = h @ w2^T)
    sgemm_tn<<<dim3(D_ / BN, T_ / BM, E_), 256>>>(
        hg, (long long)T_ * H_, H_, w2, (long long)D_ * H_, po, (long long)T_ * D_,
        D_, 0, cnt, nullptr);

    // shared FFN
    sgemm_tn<<<dim3(HS_ / BN, T_ / BM, 1), 256>>>(
        x, 0LL, D_, ws1, 0LL, sg, 0LL, HS_, T_, nullptr, nullptr);
    sgemm_tn<<<dim3(HS_ / BN, T_ / BM, 1), 256>>>(
        x, 0LL, D_, ws3, 0LL, su, 0LL, HS_, T_, nullptr, nullptr);
    swiglu_shared_kernel<<<(T_ * (HS_ / 4)) / 256, 256>>>();
    sgemm_tn<<<dim3(D_ / BN, T_ / BM, 1), 256>>>(
        sg, 0LL, HS_, ws2, 0LL, out, 0LL, D_, T_, nullptr, nullptr);

    // deterministic combine (fixed k order per token)
    combine_kernel<<<T_, 256>>>(out);
}

// round 4
// speedup vs baseline: 1.6162x; 1.6162x over previous
#include <cuda_runtime.h>
#include <cuda_bf16.h>
#include <float.h>
#include <math.h>
#include <cstdint>

#define T_   2048
#define D_   1024
#define H_   704
#define E_   16
#define HS_  1408
#define KSEL 4
#define ROUTE_SCALE_ 2.5446f

// ---------------- static device scratch (no runtime allocation) ----------------
__device__ float g_hg[(size_t)E_ * T_ * H_];   // routed gate-proj fp32
__device__ float g_hu[(size_t)E_ * T_ * H_];   // routed up-proj fp32
__device__ float g_po[(size_t)E_ * T_ * D_];   // routed down-proj per pair fp32
__device__ float g_sg[(size_t)T_ * HS_];       // shared gate-proj fp32
__device__ float g_su[(size_t)T_ * HS_];       // shared up-proj fp32
__device__ int   g_cnt[E_];
__device__ int   g_etok[E_ * T_];
__device__ int   g_slot[T_ * KSEL];
__device__ float g_wt[T_ * KSEL];

// bf16 hi/lo versions of inputs & intermediates
__device__ __nv_bfloat16 g_xh[(size_t)T_ * D_],  g_xl[(size_t)T_ * D_];
__device__ __nv_bfloat16 g_w1h[(size_t)E_ * H_ * D_], g_w1l[(size_t)E_ * H_ * D_];
__device__ __nv_bfloat16 g_w3h[(size_t)E_ * H_ * D_], g_w3l[(size_t)E_ * H_ * D_];
__device__ __nv_bfloat16 g_w2h[(size_t)E_ * D_ * H_], g_w2l[(size_t)E_ * D_ * H_];
__device__ __nv_bfloat16 g_ws1h[(size_t)HS_ * D_], g_ws1l[(size_t)HS_ * D_];
__device__ __nv_bfloat16 g_ws3h[(size_t)HS_ * D_], g_ws3l[(size_t)HS_ * D_];
__device__ __nv_bfloat16 g_ws2h[(size_t)D_ * HS_], g_ws2l[(size_t)D_ * HS_];
__device__ __nv_bfloat16 g_hth[(size_t)E_ * T_ * H_], g_htl[(size_t)E_ * T_ * H_];
__device__ __nv_bfloat16 g_ssh[(size_t)T_ * HS_], g_ssl[(size_t)T_ * HS_];

// ---------------- helpers ----------------
__device__ __forceinline__ uint32_t smem_u32(const void* p) {
    uint32_t a;
    asm("{ .reg .u64 t; cvta.to.shared.u64 t, %1; cvt.u32.u64 %0, t; }" : "=r"(a) : "l"(p));
    return a;
}

#define CPA(dst, src) \
    asm volatile("cp.async.cg.shared.global [%0], [%1], 16;" :: "r"(dst), "l"(src))
#define CPC() asm volatile("cp.async.commit_group;" ::: "memory")
#define CPW(n) asm volatile("cp.async.wait_group %0;" :: "n"(n) : "memory")

#define LDSM4(R, addr) \
    asm volatile("ldmatrix.sync.aligned.m8n8.x4.shared.b16 {%0,%1,%2,%3}, [%4];" \
        : "=r"((R)[0]), "=r"((R)[1]), "=r"((R)[2]), "=r"((R)[3]) : "r"(addr))

__device__ __forceinline__ void mma16816(float* c, const uint32_t* a, const uint32_t* b) {
    asm volatile(
        "mma.sync.aligned.m16n8k16.row.col.f32.bf16.bf16.f32 "
        "{%0,%1,%2,%3}, {%4,%5,%6,%7}, {%8,%9}, {%0,%1,%2,%3};"
        : "+f"(c[0]), "+f"(c[1]), "+f"(c[2]), "+f"(c[3])
        : "r"(a[0]), "r"(a[1]), "r"(a[2]), "r"(a[3]), "r"(b[0]), "r"(b[1]));
}

// ---------------- zero counts ----------------
__global__ void zero_cnt_kernel() {
    if (threadIdx.x < E_) g_cnt[threadIdx.x] = 0;
}

// ---------------- fp32 -> bf16 hi/lo split ----------------
__global__ void conv_kernel(const float* __restrict__ in,
                            __nv_bfloat16* __restrict__ hi,
                            __nv_bfloat16* __restrict__ lo, size_t n4) {
    size_t i = (size_t)blockIdx.x * blockDim.x + threadIdx.x;
    if (i >= n4) return;
    float4 v = ((const float4*)in)[i];
    __nv_bfloat16 h0 = __float2bfloat16(v.x);
    __nv_bfloat16 h1 = __float2bfloat16(v.y);
    __nv_bfloat16 h2 = __float2bfloat16(v.z);
    __nv_bfloat16 h3 = __float2bfloat16(v.w);
    __nv_bfloat16 l0 = __float2bfloat16(v.x - __bfloat162float(h0));
    __nv_bfloat16 l1 = __float2bfloat16(v.y - __bfloat162float(h1));
    __nv_bfloat16 l2 = __float2bfloat16(v.z - __bfloat162float(h2));
    __nv_bfloat16 l3 = __float2bfloat16(v.w - __bfloat162float(h3));
    ((__nv_bfloat162*)hi)[2 * i]     = __nv_bfloat162(h0, h1);
    ((__nv_bfloat162*)hi)[2 * i + 1] = __nv_bfloat162(h2, h3);
    ((__nv_bfloat162*)lo)[2 * i]     = __nv_bfloat162(l0, l1);
    ((__nv_bfloat162*)lo)[2 * i + 1] = __nv_bfloat162(l2, l3);
}

// ---------------- gate: logits + DeepSeek-V3 routing + dispatch ----------------
__global__ void gate_kernel(const float* __restrict__ x,
                            const float* __restrict__ gw,
                            const float* __restrict__ gb) {
    __shared__ __align__(16) float xs[8][D_];
    const int warp = threadIdx.x >> 5;
    const int lane = threadIdx.x & 31;
    const int t = blockIdx.x * 8 + warp;

    const float* xr = x + (size_t)t * D_;
    for (int i = lane; i < D_ / 4; i += 32)
        ((float4*)xs[warp])[i] = ((const float4*)xr)[i];
    __syncwarp();

    float lgv[E_];
#pragma unroll
    for (int e = 0; e < E_; e++) {
        const float* wr = gw + (size_t)e * D_;
        float p = 0.f;
        for (int i = lane; i < D_; i += 32) p += xs[warp][i] * wr[i];
#pragma unroll
        for (int o = 16; o; o >>= 1) p += __shfl_xor_sync(0xffffffffu, p, o);
        lgv[e] = p;
    }

    if (lane == 0) {
        float sc[E_], r[E_];
#pragma unroll
        for (int e = 0; e < E_; e++) {
            sc[e] = 1.f / (1.f + expf(-lgv[e]));
            r[e]  = sc[e] + gb[e];
        }
        float gs[4];
#pragma unroll
        for (int g = 0; g < 4; g++) {
            float m1 = -FLT_MAX, m2 = -FLT_MAX;
#pragma unroll
            for (int j = 0; j < 4; j++) {
                float v = r[4 * g + j];
                if (v > m1) { m2 = m1; m1 = v; }
                else if (v > m2) { m2 = v; }
            }
            gs[g] = m1 + m2;
        }
        int g1 = 0;
#pragma unroll
        for (int g = 1; g < 4; g++) if (gs[g] > gs[g1]) g1 = g;
        int g2 = -1;
#pragma unroll
        for (int g = 0; g < 4; g++) {
            if (g == g1) continue;
            if (g2 < 0 || gs[g] > gs[g2]) g2 = g;
        }
#pragma unroll
        for (int e = 0; e < E_; e++) {
            int g = e >> 2;
            if (g != g1 && g != g2) r[e] = -FLT_MAX;
        }
        int idx[KSEL];
        float wsum = 0.f;
#pragma unroll
        for (int k = 0; k < KSEL; k++) {
            int b = 0; float bv = -FLT_MAX;
#pragma unroll
            for (int e = 0; e < E_; e++)
                if (r[e] > bv) { bv = r[e]; b = e; }
            idx[k] = b;
            r[b] = -FLT_MAX;
            wsum += sc[b];
        }
        wsum = fmaxf(wsum, 1e-9f);
#pragma unroll
        for (int k = 0; k < KSEL; k++) {
            int e = idx[k];
            float wk = sc[e] / wsum * ROUTE_SCALE_;
            int pos = atomicAdd(&g_cnt[e], 1);
            g_etok[e * T_ + pos] = t;
            g_slot[t * KSEL + k] = e * T_ + pos;
            g_wt[t * KSEL + k]   = wk;
        }
    }
}

// ---------------- mma.sync bf16x3 GEMM: C[M,N] = A[M,K] * B[N,K]^T ----------------
// CTA tile 128x128x32, 256 threads = 8 warps (2 m x 4 n), warp tile 64x32.
// SMEM: per stage 4 matrices (Ah, Al, Bh, Bl), each 128 rows x 80B (32 bf16 + pad).
#define MATB   10240           // 128 * 80
#define STAGEB 40960           // 4 * MATB
#define GSMEM  81920           // 2 stages

__global__ __launch_bounds__(256) void mma_gemm(
    const __nv_bfloat16* __restrict__ Ah, const __nv_bfloat16* __restrict__ Al, long long aZ,
    const __nv_bfloat16* __restrict__ Bh, const __nv_bfloat16* __restrict__ Bl, long long bZ,
    float* __restrict__ C, long long cZ, int N, int Kd, int M,
    const int* __restrict__ cnt, const int* __restrict__ gather, int nCheck) {
    extern __shared__ char smem[];
    const uint32_t sb = smem_u32(smem);
    const int tid = threadIdx.x;
    const int z = blockIdx.z;
    const int Me = cnt ? cnt[z] : M;
    const int m0 = blockIdx.y * 128;
    if (m0 >= Me) return;
    const int n0 = blockIdx.x * 128;

    // ---- load-side mapping: thread -> (2 rows x 1 seg) per matrix ----
    const int lr = tid >> 2, seg = tid & 3;
    int ar0 = m0 + lr, ar1 = m0 + lr + 64;
    if (gather) {
        ar0 = gather[z * T_ + (ar0 < Me ? ar0 : Me - 1)];
        ar1 = gather[z * T_ + (ar1 < Me ? ar1 : Me - 1)];
    }
    int br0 = n0 + lr;      if (br0 >= N) br0 = N - 1;
    int br1 = n0 + lr + 64; if (br1 >= N) br1 = N - 1;

    const __nv_bfloat16* a0h = Ah + (size_t)z * aZ + (size_t)ar0 * Kd;
    const __nv_bfloat16* a1h = Ah + (size_t)z * aZ + (size_t)ar1 * Kd;
    const __nv_bfloat16* a0l = Al + (size_t)z * aZ + (size_t)ar0 * Kd;
    const __nv_bfloat16* a1l = Al + (size_t)z * aZ + (size_t)ar1 * Kd;
    const __nv_bfloat16* b0h = Bh + (size_t)z * bZ + (size_t)br0 * Kd;
    const __nv_bfloat16* b1h = Bh + (size_t)z * bZ + (size_t)br1 * Kd;
    const __nv_bfloat16* b0l = Bl + (size_t)z * bZ + (size_t)br0 * Kd;
    const __nv_bfloat16* b1l = Bl + (size_t)z * bZ + (size_t)br1 * Kd;

    const uint32_t d0 = sb + (uint32_t)lr * 80 + (uint32_t)seg * 16;
    const uint32_t d1 = d0 + 64 * 80;

#define LOAD_STAGE(s, kt) do { \
        const int _ko = (kt) * 32 + seg * 8; \
        const uint32_t _o = (uint32_t)(s) * STAGEB; \
        CPA(d0 + _o,            a0h + _ko); \
        CPA(d1 + _o,            a1h + _ko); \
        CPA(d0 + _o + MATB,     a0l + _ko); \
        CPA(d1 + _o + MATB,     a1l + _ko); \
        CPA(d0 + _o + 2*MATB,   b0h + _ko); \
        CPA(d1 + _o + 2*MATB,   b1h + _ko); \
        CPA(d0 + _o + 3*MATB,   b0l + _ko); \
        CPA(d1 + _o + 3*MATB,   b1l + _ko); \
    } while (0)

    // ---- compute-side mapping ----
    const int lane = tid & 31, wid = tid >> 5;
    const int wm = (wid & 1) * 64;        // warp m offset (64 rows)
    const int wn = (wid >> 1) * 32;       // warp n offset (32 cols)

    // ldmatrix lane address bases (byte offsets inside a matrix)
    const uint32_t a_rowoff = (uint32_t)(wm + (lane & 15)) * 80 + (uint32_t)(lane >> 4) * 16;
    const uint32_t b_rowoff = (uint32_t)(wn + ((lane >> 4) & 1) * 8 + (lane & 7)) * 80
                            + (uint32_t)((lane >> 3) & 1) * 16;

    float acc[4][4][4];
#pragma unroll
    for (int i = 0; i < 4; i++)
#pragma unroll
        for (int j = 0; j < 4; j++)
#pragma unroll
            for (int q = 0; q < 4; q++) acc[i][j][q] = 0.f;

    const int KT = Kd / 32;
    LOAD_STAGE(0, 0);
    CPC();

    for (int kt = 0; kt < KT; kt++) {
        if (kt + 1 < KT) { LOAD_STAGE((kt + 1) & 1, kt + 1); CPC(); CPW(1); }
        else             { CPW(0); }
        __syncthreads();

        const uint32_t base = sb + (uint32_t)(kt & 1) * STAGEB;
#pragma unroll
        for (int kk = 0; kk < 2; kk++) {
            const uint32_t kb = (uint32_t)kk * 32;  // 16 bf16 = 32B per k16 slice
            uint32_t ah[4][4], al[4][4];
#pragma unroll
            for (int mf = 0; mf < 4; mf++) {
                const uint32_t ao = base + a_rowoff + (uint32_t)mf * (16 * 80) + kb;
                LDSM4(ah[mf], ao);
                LDSM4(al[mf], ao + MATB);
            }
            uint32_t bh_[2][4], bl_[2][4];
#pragma unroll
            for (int p = 0; p < 2; p++) {
                const uint32_t bo = base + 2 * MATB + b_rowoff + (uint32_t)p * (16 * 80) + kb;
                LDSM4(bh_[p], bo);
                LDSM4(bl_[p], bo + MATB);
            }
#pragma unroll
            for (int mf = 0; mf < 4; mf++) {
#pragma unroll
                for (int nf = 0; nf < 4; nf++) {
                    const uint32_t* bh2 = &bh_[nf >> 1][(nf & 1) * 2];
                    const uint32_t* bl2 = &bl_[nf >> 1][(nf & 1) * 2];
                    mma16816(acc[mf][nf], ah[mf], bh2);
                    mma16816(acc[mf][nf], ah[mf], bl2);
                    mma16816(acc[mf][nf], al[mf], bh2);
                }
            }
        }
        __syncthreads();
    }
#undef LOAD_STAGE

    // ---- store ----
    const int srow = m0 + wm + (lane >> 2);
    const int scol = n0 + wn + (lane & 3) * 2;
    float* Cz = C + (size_t)z * cZ;
#pragma unroll
    for (int mf = 0; mf < 4; mf++) {
#pragma unroll
        for (int nf = 0; nf < 4; nf++) {
            const int col = scol + nf * 8;
            if (nCheck && col >= N) continue;
            float2 v0 = make_float2(acc[mf][nf][0], acc[mf][nf][1]);
            float2 v1 = make_float2(acc[mf][nf][2], acc[mf][nf][3]);
            *(float2*)(Cz + (size_t)(srow + mf * 16) * N + col)     = v0;
            *(float2*)(Cz + (size_t)(srow + mf * 16 + 8) * N + col) = v1;
        }
    }
}

// ---------------- SwiGLU elementwise -> bf16 hi/lo ----------------
__device__ __forceinline__ void swiglu4_store(float4 g, float4 u,
                                              __nv_bfloat16* hi, __nv_bfloat16* lo, size_t i) {
    float s0 = g.x / (1.f + expf(-g.x)) * u.x;
    float s1 = g.y / (1.f + expf(-g.y)) * u.y;
    float s2 = g.z / (1.f + expf(-g.z)) * u.z;
    float s3 = g.w / (1.f + expf(-g.w)) * u.w;
    __nv_bfloat16 h0 = __float2bfloat16(s0), h1 = __float2bfloat16(s1);
    __nv_bfloat16 h2 = __float2bfloat16(s2), h3 = __float2bfloat16(s3);
    ((__nv_bfloat162*)hi)[2 * i]     = __nv_bfloat162(h0, h1);
    ((__nv_bfloat162*)hi)[2 * i + 1] = __nv_bfloat162(h2, h3);
    ((__nv_bfloat162*)lo)[2 * i] = __nv_bfloat162(
        __float2bfloat16(s0 - __bfloat162float(h0)), __float2bfloat16(s1 - __bfloat162float(h1)));
    ((__nv_bfloat162*)lo)[2 * i + 1] = __nv_bfloat162(
        __float2bfloat16(s2 - __bfloat162float(h2)), __float2bfloat16(s3 - __bfloat162float(h3)));
}

__global__ void swiglu_routed_kernel() {
    size_t i = (size_t)blockIdx.x * blockDim.x + threadIdx.x;  // float4 idx
    int rowtile = (int)(i / (H_ / 4));
    int e = rowtile >> 11;
    int r = rowtile & (T_ - 1);
    if (r >= g_cnt[e]) return;
    float4 g = ((const float4*)g_hg)[i];
    float4 u = ((const float4*)g_hu)[i];
    swiglu4_store(g, u, g_hth, g_htl, i);
}

__global__ void swiglu_shared_kernel() {
    size_t i = (size_t)blockIdx.x * blockDim.x + threadIdx.x;
    float4 g = ((const float4*)g_sg)[i];
    float4 u = ((const float4*)g_su)[i];
    swiglu4_store(g, u, g_ssh, g_ssl, i);
}

// ---------------- combine: out += sum_k w_k * pair_out[slot_k] ----------------
__global__ void combine_kernel(float* __restrict__ out) {
    int t = blockIdx.x;
    int c = threadIdx.x;   // 0..255 float4 columns
    float4 a = ((float4*)out)[(size_t)t * (D_ / 4) + c];
#pragma unroll
    for (int k = 0; k < KSEL; k++) {
        int s = g_slot[t * KSEL + k];
        float wk = g_wt[t * KSEL + k];
        float4 v = ((const float4*)g_po)[(size_t)s * (D_ / 4) + c];
        a.x += wk * v.x; a.y += wk * v.y; a.z += wk * v.z; a.w += wk * v.w;
    }
    ((float4*)out)[(size_t)t * (D_ / 4) + c] = a;
}

// ---------------- launch ----------------
static void conv_launch(const float* in, __nv_bfloat16* hi, __nv_bfloat16* lo, size_t n) {
    size_t n4 = n / 4;
    conv_kernel<<<(unsigned)((n4 + 255) / 256), 256>>>(in, hi, lo, n4);
}

extern "C" void kernel_launch(void* const* d_in, const int* in_sizes, int n_in,
                              void* d_out, int out_size) {
    (void)in_sizes; (void)n_in; (void)out_size;
    const float* x   = (const float*)d_in[0];
    const float* gw  = (const float*)d_in[1];
    const float* gb  = (const float*)d_in[2];
    const float* w1  = (const float*)d_in[3];
    const float* w3  = (const float*)d_in[4];
    const float* w2  = (const float*)d_in[5];
    const float* ws1 = (const float*)d_in[6];
    const float* ws3 = (const float*)d_in[7];
    const float* ws2 = (const float*)d_in[8];
    float* out = (float*)d_out;

    cudaFuncSetAttribute(mma_gemm, cudaFuncAttributeMaxDynamicSharedMemorySize, GSMEM);

    float *hg, *hu, *po, *sg, *su;
    int *cnt, *etok;
    __nv_bfloat16 *xh, *xl, *w1h, *w1l, *w3h, *w3l, *w2h, *w2l;
    __nv_bfloat16 *ws1h, *ws1l, *ws3h, *ws3l, *ws2h, *ws2l;
    __nv_bfloat16 *hth, *htl, *ssh, *ssl;
    cudaGetSymbolAddress((void**)&hg, g_hg);   cudaGetSymbolAddress((void**)&hu, g_hu);
    cudaGetSymbolAddress((void**)&po, g_po);   cudaGetSymbolAddress((void**)&sg, g_sg);
    cudaGetSymbolAddress((void**)&su, g_su);   cudaGetSymbolAddress((void**)&cnt, g_cnt);
    cudaGetSymbolAddress((void**)&etok, g_etok);
    cudaGetSymbolAddress((void**)&xh, g_xh);   cudaGetSymbolAddress((void**)&xl, g_xl);
    cudaGetSymbolAddress((void**)&w1h, g_w1h); cudaGetSymbolAddress((void**)&w1l, g_w1l);
    cudaGetSymbolAddress((void**)&w3h, g_w3h); cudaGetSymbolAddress((void**)&w3l, g_w3l);
    cudaGetSymbolAddress((void**)&w2h, g_w2h); cudaGetSymbolAddress((void**)&w2l, g_w2l);
    cudaGetSymbolAddress((void**)&ws1h, g_ws1h); cudaGetSymbolAddress((void**)&ws1l, g_ws1l);
    cudaGetSymbolAddress((void**)&ws3h, g_ws3h); cudaGetSymbolAddress((void**)&ws3l, g_ws3l);
    cudaGetSymbolAddress((void**)&ws2h, g_ws2h); cudaGetSymbolAddress((void**)&ws2l, g_ws2l);
    cudaGetSymbolAddress((void**)&hth, g_hth); cudaGetSymbolAddress((void**)&htl, g_htl);
    cudaGetSymbolAddress((void**)&ssh, g_ssh); cudaGetSymbolAddress((void**)&ssl, g_ssl);

    // conversions (independent of gate)
    conv_launch(x,   xh,   xl,   (size_t)T_ * D_);
    conv_launch(w1,  w1h,  w1l,  (size_t)E_ * H_ * D_);
    conv_launch(w3,  w3h,  w3l,  (size_t)E_ * H_ * D_);
    conv_launch(w2,  w2h,  w2l,  (size_t)E_ * D_ * H_);
    conv_launch(ws1, ws1h, ws1l, (size_t)HS_ * D_);
    conv_launch(ws3, ws3h, ws3l, (size_t)HS_ * D_);
    conv_launch(ws2, ws2h, ws2l, (size_t)D_ * HS_);

    zero_cnt_kernel<<<1, 32>>>();
    gate_kernel<<<T_ / 8, 256>>>(x, gw, gb);

    // routed gate & up projections: [cnt_e x H] = gather(x) @ w1/w3^T   (N=704 -> edge check)
    mma_gemm<<<dim3((H_ + 127) / 128, T_ / 128, E_), 256, GSMEM>>>(
        xh, xl, 0LL, w1h, w1l, (long long)H_ * D_, hg, (long long)T_ * H_, H_, D_, 0, cnt, etok, 1);
    mma_gemm<<<dim3((H_ + 127) / 128, T_ / 128, E_), 256, GSMEM>>>(
        xh, xl, 0LL, w3h, w3l, (long long)H_ * D_, hu, (long long)T_ * H_, H_, D_, 0, cnt, etok, 1);
    swiglu_routed_kernel<<<(E_ * T_ * (H_ / 4)) / 256, 256>>>();
    // routed down projection: [cnt_e x D] = h @ w2^T
    mma_gemm<<<dim3(D_ / 128, T_ / 128, E_), 256, GSMEM>>>(
        hth, htl, (long long)T_ * H_, w2h, w2l, (long long)D_ * H_, po, (long long)T_ * D_,
        D_, H_, 0, cnt, nullptr, 0);

    // shared FFN
    mma_gemm<<<dim3(HS_ / 128, T_ / 128, 1), 256, GSMEM>>>(
        xh, xl, 0LL, ws1h, ws1l, 0LL, sg, 0LL, HS_, D_, T_, nullptr, nullptr, 0);
    mma_gemm<<<dim3(HS_ / 128, T_ / 128, 1), 256, GSMEM>>>(
        xh, xl, 0LL, ws3h, ws3l, 0LL, su, 0LL, HS_, D_, T_, nullptr, nullptr, 0);
    swiglu_shared_kernel<<<(T_ * (HS_ / 4)) / 256, 256>>>();
    mma_gemm<<<dim3(D_ / 128, T_ / 128, 1), 256, GSMEM>>>(
        ssh, ssl, 0LL, ws2h, ws2l, 0LL, out, 0LL, D_, HS_, T_, nullptr, nullptr, 0);

    combine_kernel<<<T_, 256>>>(out);
}